// round 7
// baseline (speedup 1.0000x reference)
#include <cuda_runtime.h>

// ---------------- problem constants ----------------
#define NN    100           // nodes
#define BATCH 32
#define HID   32
#define DD    3200          // N*H
#define NSPLIT 20           // split-K factor for the big GEMM
#define TO    128           // o-tile per CTA
#define IB    4             // i-block

// ---------------- device scratch (no allocations allowed) ----------------
__device__ float g_A[NN * NN];
__device__ float g_hs[BATCH * DD];
__device__ float g_gates[BATCH * 3];
__device__ __align__(16) float g_act[(long)DD * 16 * BATCH];      // [i][c][b]  6.55 MB
__device__ float g_partial[(long)NSPLIT * BATCH * DD];            // 8.19 MB

// ==========================================================================
// K1: alpha = sigmoid(mean_b inputs), A[m,n] = alpha[n]*lap + (1-alpha[n])*corr
// ==========================================================================
__global__ void k1_alpha_A(const float* __restrict__ inputs,
                           const float* __restrict__ lap,
                           const float* __restrict__ corr) {
    __shared__ float sa[NN];
    int t = threadIdx.x;
    if (t < NN) {
        float s = 0.f;
        for (int b = 0; b < BATCH; b++) s += inputs[b * NN + t];
        sa[t] = 1.f / (1.f + expf(-s * (1.f / BATCH)));
    }
    __syncthreads();
    for (int idx = t; idx < NN * NN; idx += blockDim.x) {
        int n = idx % NN;
        float a = sa[n];
        g_A[idx] = a * lap[idx] + (1.f - a) * corr[idx];
    }
}

// ==========================================================================
// K2: ax = A @ concat(inputs, hidden); h = ax @ gc_w + gc_b; layernorm -> g_hs
// one block per (b, m)
// ==========================================================================
__global__ void k2_gconv_ln(const float* __restrict__ inputs,
                            const float* __restrict__ hidden,
                            const float* __restrict__ gc_w,
                            const float* __restrict__ gc_b,
                            const float* __restrict__ ln_g,
                            const float* __restrict__ ln_b) {
    __shared__ float ax[HID + 1];
    int bi = blockIdx.x;
    int b = bi / NN, m = bi % NN;
    int t = threadIdx.x;
    if (t < HID + 1) {
        float s = 0.f;
        const float* Arow = g_A + m * NN;
        for (int n = 0; n < NN; n++) {
            float cf = (t == 0) ? inputs[b * NN + n]
                                : hidden[(b * NN + n) * HID + (t - 1)];
            s = fmaf(Arow[n], cf, s);
        }
        ax[t] = s;
    }
    __syncthreads();
    if (t < HID) {
        float h = gc_b[t];
#pragma unroll
        for (int f = 0; f < HID + 1; f++) h = fmaf(ax[f], gc_w[f * HID + t], h);
        // warp-wide layernorm over the 32 hidden values
        float s = h;
        for (int off = 16; off; off >>= 1) s += __shfl_xor_sync(0xffffffffu, s, off);
        float mu = s * (1.f / HID);
        float d = h - mu;
        float v = d * d;
        for (int off = 16; off; off >>= 1) v += __shfl_xor_sync(0xffffffffu, v, off);
        v *= (1.f / HID);
        float r = rsqrtf(v + 1e-5f);
        g_hs[b * DD + m * HID + t] = d * r * ln_g[t] + ln_b[t];
    }
}

// ==========================================================================
// K3: gating scores (DFT-magnitude, smoothness, nonlinearity) -> softmax gates
// one block per batch
// ==========================================================================
__global__ void k3_gating(const float* __restrict__ minp, const float* __restrict__ maxp,
                          const float* __restrict__ mins, const float* __restrict__ maxs,
                          const float* __restrict__ minn, const float* __restrict__ maxn) {
    __shared__ float sh[DD];
    __shared__ float ct[100], st[100];
    __shared__ float red[3][8];
    int b = blockIdx.x, t = threadIdx.x;
    for (int i = t; i < DD; i += 256) sh[i] = g_hs[b * DD + i];
    if (t < 100) {
        // e^{-2*pi*i*k*t/10}: cos(2pi*k*t/10) = cospi(0.2*k*t)
        float ang = 0.2f * (float)((t / 10) * (t % 10));
        ct[t] = cospif(ang);
        st[t] = sinpif(ang);
    }
    __syncthreads();

    float ps = 0.f, ss = 0.f, ns = 0.f;
    // p: mean |FFT| over 1596 windows x 10 freqs
    for (int idx = t; idx < 15960; idx += 256) {
        int w = idx / 10, k = idx % 10;
        const float* x = sh + 2 * w;
        float re = 0.f, im = 0.f;
#pragma unroll
        for (int tt = 0; tt < 10; tt++) {
            re = fmaf(x[tt], ct[k * 10 + tt], re);
            im = fmaf(x[tt], st[k * 10 + tt], im);
        }
        ps += sqrtf(re * re + im * im);
    }
    // s: mean |diff| within windows
    for (int w = t; w < 1596; w += 256) {
        const float* x = sh + 2 * w;
#pragma unroll
        for (int tt = 0; tt < 9; tt++) ss += fabsf(x[tt + 1] - x[tt]);
    }
    // n: mean |2nd diff| over D
    for (int i = t; i < DD - 2; i += 256)
        ns += fabsf(sh[i + 2] - 2.f * sh[i + 1] + sh[i]);

    for (int off = 16; off; off >>= 1) {
        ps += __shfl_xor_sync(0xffffffffu, ps, off);
        ss += __shfl_xor_sync(0xffffffffu, ss, off);
        ns += __shfl_xor_sync(0xffffffffu, ns, off);
    }
    if ((t & 31) == 0) { red[0][t >> 5] = ps; red[1][t >> 5] = ss; red[2][t >> 5] = ns; }
    __syncthreads();
    if (t == 0) {
        float P = 0.f, S = 0.f, Q = 0.f;
        for (int w = 0; w < 8; w++) { P += red[0][w]; S += red[1][w]; Q += red[2][w]; }
        float p_raw = P / 15960.f;
        float s_raw = S / 14364.f;          // 1596*9
        float n_raw = Q / 3198.f;
        float p = fabsf((p_raw - *minp) / (*maxp - *minp + 1e-8f));
        float s = 1.f - fabsf((s_raw - *mins) / (*maxs - *mins + 1e-8f));
        float n = fabsf((n_raw - *minn) / (*maxn - *minn + 1e-8f));
        float a0 = fabsf(p), a1 = fabsf(s), a2 = fabsf(n);
        float m = fmaxf(a0, fmaxf(a1, a2));
        float e0 = expf(a0 - m), e1 = expf(a1 - m), e2 = expf(a2 - m);
        float inv = 1.f / (e0 + e1 + e2);
        g_gates[b * 3 + 0] = e0 * inv;
        g_gates[b * 3 + 1] = e1 * inv;
        g_gates[b * 3 + 2] = e2 * inv;
    }
}

// ==========================================================================
// K4: per-element expert basis activations -> g_act[i][c][b], 16 channels:
// c0..3 Chebyshev T_d(tanh(xc)), c4 silu(xb), c5..12 B-spline bases, c13..15 xt^{1..3}
// ==========================================================================
__global__ void k4_act() {
    int t = threadIdx.x;
    int b = t & 31;
    int i = blockIdx.x * 8 + (t >> 5);
    float x = g_hs[b * DD + i];
    float g0 = g_gates[b * 3 + 0], g1 = g_gates[b * 3 + 1], g2 = g_gates[b * 3 + 2];
    float xc = g0 * x, xb = g1 * x, xt = g2 * x;

    float v[16];
    // Chebyshev: cos(d * arccos(tanh(xc))) == T_d(tanh(xc))
    float tc = tanhf(xc);
    v[0] = 1.f;
    v[1] = tc;
    v[2] = 2.f * tc * tc - 1.f;
    v[3] = tc * (4.f * tc * tc - 3.f);
    // silu
    v[4] = xb / (1.f + expf(-xb));
    // B-spline bases, Cox-de Boor, GRID_SIZE=5, K=3, grid j=(j-3)*0.4-1
    float gr[12];
#pragma unroll
    for (int j = 0; j < 12; j++) gr[j] = (float)(j - 3) * 0.4f - 1.f;
    float bs[11];
#pragma unroll
    for (int j = 0; j < 11; j++) bs[j] = (xb >= gr[j] && xb < gr[j + 1]) ? 1.f : 0.f;
#pragma unroll
    for (int d = 1; d <= 3; d++) {
#pragma unroll
        for (int j = 0; j < 11 - 1; j++) {
            if (j < 11 - d) {
                bs[j] = (xb - gr[j]) / (gr[j + d] - gr[j]) * bs[j]
                      + (gr[j + d + 1] - xb) / (gr[j + d + 1] - gr[j + 1]) * bs[j + 1];
            }
        }
    }
#pragma unroll
    for (int k = 0; k < 8; k++) v[5 + k] = bs[k];
    // Taylor powers
    v[13] = xt;
    v[14] = xt * xt;
    v[15] = xt * xt * xt;

    float* dst = g_act + (long)i * (16 * BATCH) + b;
#pragma unroll
    for (int c = 0; c < 16; c++) dst[c * 32] = v[c];
}

// ==========================================================================
// K6: fused skinny GEMM: out[b,o] = sum_{i,c} Act[b,i,c] * W_c[i,o]
//   W: c0..3 cheb_c[i,o,c] | c4 base_w[o,i] | c5..12 spline_w[o,i,k] | c13..15 taylor_c[i,o,p]
// CTA: 128 threads, o-tile = 128, all 32 b. Thread: 8 b x 4 o register tile.
// Split-K over NSPLIT ranges -> deterministic partial buffers.
// ==========================================================================
__global__ void __launch_bounds__(128, 1) k6_gemm(const float* __restrict__ cheb,
                                                  const float* __restrict__ base,
                                                  const float* __restrict__ spline,
                                                  const float* __restrict__ taylor) {
    __shared__ float ws[IB][16][TO];                       // 32 KB
    __shared__ __align__(16) float as_[IB][16][BATCH];     // 8 KB
    int t = threadIdx.x;
    int ot = blockIdx.x % (DD / TO);       // 25 o-tiles
    int sp = blockIdx.x / (DD / TO);       // NSPLIT splits
    int o0 = ot * TO;
    int i0 = sp * (DD / NSPLIT);           // 160 i per split
    int lane = t & 31;
    int bb = (t >> 5) << 3;                // warp -> 8-batch group
    int o = o0 + t;

    float acc[8][4];
#pragma unroll
    for (int j = 0; j < 8; j++)
#pragma unroll
        for (int oo = 0; oo < 4; oo++) acc[j][oo] = 0.f;

    for (int ib = 0; ib < (DD / NSPLIT) / IB; ib++) {      // 40 blocks
        int ibase = i0 + ib * IB;
        // ---- cooperative weight staging (mixed layouts -> [il][c][o]) ----
#pragma unroll
        for (int il = 0; il < IB; il++) {
            int i = ibase + il;
            float4 cv = *(const float4*)(cheb + ((long)i * DD + o) * 4);
            ws[il][0][t] = cv.x; ws[il][1][t] = cv.y; ws[il][2][t] = cv.z; ws[il][3][t] = cv.w;
            const float* tp = taylor + ((long)i * DD + o) * 3;
            ws[il][13][t] = tp[0]; ws[il][14][t] = tp[1]; ws[il][15][t] = tp[2];
        }
        {
            float4 bv = *(const float4*)(base + (long)o * DD + ibase);
            ws[0][4][t] = bv.x; ws[1][4][t] = bv.y; ws[2][4][t] = bv.z; ws[3][4][t] = bv.w;
            const float4* spv = (const float4*)(spline + ((long)o * DD + ibase) * 8);
#pragma unroll
            for (int q = 0; q < 8; q++) {
                float4 v = spv[q];
                int il = q >> 1;
                int c0 = 5 + (q & 1) * 4;
                ws[il][c0 + 0][t] = v.x; ws[il][c0 + 1][t] = v.y;
                ws[il][c0 + 2][t] = v.z; ws[il][c0 + 3][t] = v.w;
            }
            // activations: 4 i * 512 floats contiguous
            const float4* ap = (const float4*)(g_act + (long)ibase * (16 * BATCH));
            float4* asp = (float4*)as_;
#pragma unroll
            for (int q = 0; q < 4; q++) asp[t + 128 * q] = ap[t + 128 * q];
        }
        __syncthreads();

        // ---- compute: weights conflict-free (lane-strided), act broadcast ----
#pragma unroll
        for (int il = 0; il < IB; il++) {
#pragma unroll
            for (int c = 0; c < 16; c++) {
                float w0 = ws[il][c][lane];
                float w1 = ws[il][c][lane + 32];
                float w2 = ws[il][c][lane + 64];
                float w3 = ws[il][c][lane + 96];
#pragma unroll
                for (int j = 0; j < 8; j++) {
                    float a = as_[il][c][bb + j];
                    acc[j][0] = fmaf(a, w0, acc[j][0]);
                    acc[j][1] = fmaf(a, w1, acc[j][1]);
                    acc[j][2] = fmaf(a, w2, acc[j][2]);
                    acc[j][3] = fmaf(a, w3, acc[j][3]);
                }
            }
        }
        __syncthreads();
    }

    // ---- epilogue: deterministic per-split partials ----
#pragma unroll
    for (int j = 0; j < 8; j++) {
        int b = bb + j;
        float* dst = g_partial + ((long)sp * BATCH + b) * DD + o0;
#pragma unroll
        for (int oo = 0; oo < 4; oo++) dst[lane + oo * 32] = acc[j][oo];
    }
}

// ==========================================================================
// K7: reduce split-K partials -> output [B, N, H] (flat b*3200 + o)
// ==========================================================================
__global__ void k7_reduce(float* __restrict__ out) {
    int idx = blockIdx.x * 256 + threadIdx.x;
    if (idx < BATCH * DD) {
        float s = 0.f;
#pragma unroll
        for (int sp = 0; sp < NSPLIT; sp++) s += g_partial[(long)sp * BATCH * DD + idx];
        out[idx] = s;
    }
}

// ==========================================================================
extern "C" void kernel_launch(void* const* d_in, const int* in_sizes, int n_in,
                              void* d_out, int out_size) {
    const float* inputs = (const float*)d_in[0];
    const float* hidden = (const float*)d_in[1];
    const float* lap    = (const float*)d_in[2];
    const float* corr   = (const float*)d_in[3];
    const float* gc_w   = (const float*)d_in[4];
    const float* gc_b   = (const float*)d_in[5];
    const float* ln_g   = (const float*)d_in[6];
    const float* ln_b   = (const float*)d_in[7];
    const float* cheb   = (const float*)d_in[8];
    const float* base   = (const float*)d_in[9];
    const float* spline = (const float*)d_in[10];
    const float* taylor = (const float*)d_in[11];
    const float* minp   = (const float*)d_in[12];
    const float* maxp   = (const float*)d_in[13];
    const float* mins   = (const float*)d_in[14];
    const float* maxs   = (const float*)d_in[15];
    const float* minn   = (const float*)d_in[16];
    const float* maxn   = (const float*)d_in[17];
    float* out = (float*)d_out;

    k1_alpha_A<<<1, 256>>>(inputs, lap, corr);
    k2_gconv_ln<<<BATCH * NN, 64>>>(inputs, hidden, gc_w, gc_b, ln_g, ln_b);
    k3_gating<<<BATCH, 256>>>(minp, maxp, mins, maxs, minn, maxn);
    k4_act<<<DD / 8, 256>>>();
    k6_gemm<<<(DD / TO) * NSPLIT, 128>>>(cheb, base, spline, taylor);
    k7_reduce<<<(BATCH * DD + 255) / 256, 256>>>(out);
}